// round 13
// baseline (speedup 1.0000x reference)
#include <cuda_runtime.h>

// out[i] = in[i,1] + w*(in[i,0]-in[i,1]).  N = 16777216, pure streaming.
// Champion memory shape per iteration (R10/R12: two adjacent __ldg LDG.128 +
// __stcs STG.128, 4 outputs/thread). Structural delta: persistent grid-stride
// launch — ONE wave of 2368 CTAs (148 SMs x 16 resident 128-thread blocks),
// each thread loops ~14 iterations. Removes ~27 wave transitions and
// amortizes the w-load/prologue across the whole run.

__global__ __launch_bounds__(128)
void skip_kernel(const float4* __restrict__ in,
                 const float* __restrict__ w_ptr,
                 float4* __restrict__ out,
                 unsigned n4)
{
    const unsigned stride = gridDim.x * blockDim.x;
    const float w = __ldg(w_ptr);

    for (unsigned i = blockIdx.x * blockDim.x + threadIdx.x; i < n4; i += stride) {
        float4 a = __ldg(&in[2u * i]);
        float4 b = __ldg(&in[2u * i + 1u]);

        float4 o;
        o.x = fmaf(w, a.x - a.y, a.y);
        o.y = fmaf(w, a.z - a.w, a.w);
        o.z = fmaf(w, b.x - b.y, b.y);
        o.w = fmaf(w, b.z - b.w, b.w);

        __stcs(&out[i], o);
    }
}

extern "C" void kernel_launch(void* const* d_in, const int* in_sizes, int n_in,
                              void* d_out, int out_size)
{
    const float* input  = (const float*)d_in[0];   // [N,2]
    const float* weight = (const float*)d_in[1];   // [1,1]
    float*       out    = (float*)d_out;           // [N,1]

    const unsigned n  = (unsigned)(in_sizes[0] / 2); // 16777216 outputs
    const unsigned n4 = n / 4u;                      // float4-granular work items

    // One full wave: 148 SMs x 16 resident blocks (128 thr, 20 regs -> warp-limited)
    const int threads = 128;
    const int blocks  = 148 * 16;                    // 2368

    skip_kernel<<<blocks, threads>>>((const float4*)input, weight,
                                     (float4*)out, n4);
}

// round 14
// speedup vs baseline: 1.0502x; 1.0502x over previous
#include <cuda_runtime.h>

// FINAL — converged champion (R10/R12 config, best bench 31.2us, twice).
// out[i] = in[i,1] + w*(in[i,0]-in[i,1]).  N = 16777216, pure streaming,
// 12 B/elem. Kernel 26.3-27.0us @ 6.07-6.22 TB/s (76-78% of 8TB/s spec) =
// sm_103a effective LTS/DRAM ceiling for a 2:1 R:W stream.
//
// Exhaustive isolation matrix (13 rounds):
//   outputs/thread: 2-dense / 4 / 8      -> 4 adjacent (8 jams L1tex queue)
//   load policy: __ldg / .cs / .nc+evict_last / LDG.256 / __constant__ w
//                                         -> default __ldg (rest <= neutral)
//   store policy: default / __stcs / __stwt -> __stcs (-0.8us)
//   block: 128 / 256 / 512               -> 128 (best occupancy, 76-77%)
//   launch: flat / persistent grid-stride -> flat (persistent -2.1us worse:
//           static partitioning + loop de-batches MLP)

__global__ __launch_bounds__(128)
void skip_kernel(const float4* __restrict__ in,
                 const float* __restrict__ w_ptr,
                 float4* __restrict__ out)
{
    const unsigned i = blockIdx.x * blockDim.x + threadIdx.x;
    const float w = __ldg(w_ptr);

    float4 a = __ldg(&in[2u * i]);
    float4 b = __ldg(&in[2u * i + 1u]);

    float4 o;
    o.x = fmaf(w, a.x - a.y, a.y);
    o.y = fmaf(w, a.z - a.w, a.w);
    o.z = fmaf(w, b.x - b.y, b.y);
    o.w = fmaf(w, b.z - b.w, b.w);

    __stcs(&out[i], o);
}

extern "C" void kernel_launch(void* const* d_in, const int* in_sizes, int n_in,
                              void* d_out, int out_size)
{
    const float* input  = (const float*)d_in[0];   // [N,2]
    const float* weight = (const float*)d_in[1];   // [1,1]
    float*       out    = (float*)d_out;           // [N,1]

    const int n = in_sizes[0] / 2;     // 16777216 outputs
    const int n4 = n / 4;              // 4 outputs per thread, exact
    const int threads = 128;
    const int blocks = n4 / threads;   // 32768

    skip_kernel<<<blocks, threads>>>((const float4*)input, weight, (float4*)out);
}

// round 15
// speedup vs baseline: 1.0738x; 1.0226x over previous
#include <cuda_runtime.h>

// out[i] = in[i,1] + w*(in[i,0]-in[i,1]).  N = 16777216, pure streaming.
// Champion config (R10/R12/R14: kernel 26.3-27.3us, bench 31.2-31.9us):
// 4 outputs/thread, two adjacent LDG.128, __stcs STG.128, block 128 x 32768.
// Single delta: loads __ldg -> __ldcg (ld.global.cg: cache at L2 only,
// bypass L1 allocation — input has zero reuse and L1D is flushed per launch,
// so L1 fills are pure overhead). NOT the same as the rejected .cs variant,
// which kept L1 allocation and changed L2 policy.

__global__ __launch_bounds__(128)
void skip_kernel(const float4* __restrict__ in,
                 const float* __restrict__ w_ptr,
                 float4* __restrict__ out)
{
    const unsigned i = blockIdx.x * blockDim.x + threadIdx.x;
    const float w = __ldg(w_ptr);

    float4 a = __ldcg(&in[2u * i]);
    float4 b = __ldcg(&in[2u * i + 1u]);

    float4 o;
    o.x = fmaf(w, a.x - a.y, a.y);
    o.y = fmaf(w, a.z - a.w, a.w);
    o.z = fmaf(w, b.x - b.y, b.y);
    o.w = fmaf(w, b.z - b.w, b.w);

    __stcs(&out[i], o);
}

extern "C" void kernel_launch(void* const* d_in, const int* in_sizes, int n_in,
                              void* d_out, int out_size)
{
    const float* input  = (const float*)d_in[0];   // [N,2]
    const float* weight = (const float*)d_in[1];   // [1,1]
    float*       out    = (float*)d_out;           // [N,1]

    const int n = in_sizes[0] / 2;     // 16777216 outputs
    const int n4 = n / 4;              // 4 outputs per thread, exact
    const int threads = 128;
    const int blocks = n4 / threads;   // 32768

    skip_kernel<<<blocks, threads>>>((const float4*)input, weight, (float4*)out);
}